// round 9
// baseline (speedup 1.0000x reference)
#include <cuda_runtime.h>
#include <cuda_fp16.h>
#include <cstdint>

// Problem constants
#define B_    16
#define D_    256
#define S_    1024
#define NTOK  16384
#define KC    8192
#define BDS   4194304

#define MB_TOT (NTOK / 16)        // 1024 token blocks of 16
#define KS_TOT (D_ / 16)          // 16 k-steps of 16
#define NB_TOT (KC / 8)           // 1024 code blocks of 8

// Main kernel tiling
#define MT     128                // tokens per block
#define NT     128                // codes per n-tile
#define NPARTS 8                  // codebook split per token tile
#define NITERL 64                 // local iterations (2 k-steps each)
#define NGS    (NITERL * 2)       // 128 ksl-granular steps

// smem layout (bytes): A-tile (hi|lo) + reduction slots
#define SMEM_A_BYTES 131072       // [2 h][8 mb][16 ks][32 lane][4] u32
#define SMEM_RED     1024         // 128 x u64
#define SMEM_MAIN (SMEM_A_BYTES + SMEM_RED)

// Device scratch (allocations forbidden)
__device__ uint32_t g_Ah[MB_TOT * KS_TOT * 32 * 4];   // 8 MB
__device__ uint32_t g_Al[MB_TOT * KS_TOT * 32 * 4];   // 8 MB
__device__ uint32_t g_B [NB_TOT * KS_TOT * 32 * 4];   // 8 MB: {bh0,bh1,bl0,bl1}
__device__ float    g_csq[KC];
__device__ unsigned long long g_key[NTOK];            // packed (fkey(dist)<<32 | k)

// ---------------------------- helpers --------------------------------------
__device__ __forceinline__ uint32_t smem_u32(const void* p) {
    uint32_t a;
    asm("{ .reg .u64 t; cvta.to.shared.u64 t, %1; cvt.u32.u64 %0, t; }" : "=r"(a) : "l"(p));
    return a;
}
__device__ __forceinline__ void cpasync16(uint32_t dst, const void* src) {
    asm volatile("cp.async.cg.shared.global [%0], [%1], 16;" :: "r"(dst), "l"(src));
}
__device__ __forceinline__ void mma16816(float* c, const uint32_t* a, const uint32_t* b) {
    asm volatile("mma.sync.aligned.m16n8k16.row.col.f32.f16.f16.f32 "
                 "{%0,%1,%2,%3}, {%4,%5,%6,%7}, {%8,%9}, {%0,%1,%2,%3};"
                 : "+f"(c[0]), "+f"(c[1]), "+f"(c[2]), "+f"(c[3])
                 : "r"(a[0]), "r"(a[1]), "r"(a[2]), "r"(a[3]), "r"(b[0]), "r"(b[1]));
}
__device__ __forceinline__ uint32_t pack_h2(__half lo, __half hi) {
    __half2 h = __halves2half2(lo, hi);
    return *reinterpret_cast<uint32_t*>(&h);
}
__device__ __forceinline__ void split16(float v, __half& h, __half& l) {
    h = __float2half_rn(v);
    l = __float2half_rn(v - __half2float(h));
}
__device__ __forceinline__ unsigned int fkey(float f) {
    unsigned u = __float_as_uint(f);
    return (u & 0x80000000u) ? ~u : (u | 0x80000000u);
}

// ---------------------------------------------------------------------------
// Split x into fp16 hi/lo A-fragments (mma m16n8k16 row-major A layout).
// Also re-initializes g_key every launch (blocks 0..63).
// ---------------------------------------------------------------------------
__global__ void vq_split_x(const float* __restrict__ x) {
    __shared__ float xs[D_ * 16];            // [d][tok]
    const int mb = blockIdx.x;
    const int t0 = mb * 16;
    const int b  = t0 >> 10;
    const int s0 = t0 & (S_ - 1);
    const int tid = threadIdx.x;

    if (mb < NTOK / 256) g_key[mb * 256 + tid] = 0xFFFFFFFFFFFFFFFFULL;

    for (int i = tid; i < D_ * 16; i += 256) {
        int d = i >> 4, tok = i & 15;
        xs[d * 16 + tok] = x[((size_t)b * D_ + d) * S_ + s0 + tok];
    }
    __syncthreads();

    const size_t obase = (size_t)mb * (KS_TOT * 32 * 4);
    for (int oi = tid; oi < KS_TOT * 32 * 4; oi += 256) {
        int ks = oi >> 7, rem = oi & 127;
        int lane = rem >> 2, r = rem & 3;
        int gid = lane >> 2, tig = lane & 3;
        int row = gid + (r & 1) * 8;
        int c0  = ks * 16 + tig * 2 + (r >> 1) * 8;
        float v0 = xs[c0 * 16 + row];
        float v1 = xs[(c0 + 1) * 16 + row];
        __half h0, l0, h1, l1;
        split16(v0, h0, l0);
        split16(v1, h1, l1);
        g_Ah[obase + oi] = pack_h2(h0, h1);
        g_Al[obase + oi] = pack_h2(l0, l1);
    }
}

// ---------------------------------------------------------------------------
// Split E into interleaved fp16 hi/lo B-fragments (m16n8k16 col-major B).
// ---------------------------------------------------------------------------
__global__ void vq_split_e(const float* __restrict__ E) {
    int gidx = blockIdx.x * 256 + threadIdx.x;    // 0 .. NB_TOT*16*32
    int lane = gidx & 31;
    int ks   = (gidx >> 5) & 15;
    int nb   = gidx >> 9;
    int gid = lane >> 2, tig = lane & 3;
    int k = nb * 8 + gid;
    uint32_t frag[4];
#pragma unroll
    for (int r = 0; r < 2; ++r) {
        int d0 = ks * 16 + tig * 2 + r * 8;
        float v0 = E[(size_t)d0 * KC + k];
        float v1 = E[(size_t)(d0 + 1) * KC + k];
        __half h0, l0, h1, l1;
        split16(v0, h0, l0);
        split16(v1, h1, l1);
        frag[r]     = pack_h2(h0, h1);
        frag[2 + r] = pack_h2(l0, l1);
    }
    *(uint4*)&g_B[(size_t)gidx * 4] = *(uint4*)frag;
}

// ---------------------------------------------------------------------------
__global__ void vq_csq_kernel(const float* __restrict__ E) {
    int k = blockIdx.x * blockDim.x + threadIdx.x;
    float a = 0.f;
#pragma unroll 8
    for (int d = 0; d < D_; ++d) {
        float v = E[(size_t)d * KC + k];
        a = fmaf(v, v, a);
    }
    g_csq[k] = a;
}

// ---------------------------------------------------------------------------
// Main kernel: 512 threads (16 warps, 4m x 4n), MT=128 A-tile in smem.
// B register-pipelined at ksl granularity via LDG.128; barrier-free mainloop.
// ---------------------------------------------------------------------------
__device__ __forceinline__ void loadB_step(uint4* b, int it, int ks,
                                           int nwarp, int lane) {
    const uint32_t* base = g_B +
        ((size_t)((((it >> 3) * 16 + nwarp * 4) * 16 + ks) * 32 + lane)) * 4;
#pragma unroll
    for (int nf = 0; nf < 4; ++nf)
        b[nf] = __ldg((const uint4*)(base + nf * 2048));
}

__global__ __launch_bounds__(512, 1) void vq_mma_kernel() {
    extern __shared__ char smem[];
    uint32_t* As = (uint32_t*)smem;
    unsigned long long* red = (unsigned long long*)(smem + SMEM_A_BYTES);
    const uint32_t sA = smem_u32(As);

    const int tid = threadIdx.x;
    const int wid = tid >> 5, lane = tid & 31;
    const int gid = lane >> 2, tig = lane & 3;
    const int mwarp = wid >> 2, nwarp = wid & 3;

    const int bx = blockIdx.x;                // 0..1023
    const int part   = bx & (NPARTS - 1);     // codebook eighth
    const int tileid = bx >> 3;               // token tile
    const int mb0 = tileid * 8;
    const int n0  = tileid * MT;
    const int it0 = part * NITERL;            // global iteration base

    if (tid < MT) red[tid] = 0xFFFFFFFFFFFFFFFFULL;

    // Prologue: A resident tile (hi+lo, 128 KB) via cp.async; single barrier.
    {
        const uint32_t* srcH = g_Ah + (size_t)mb0 * (KS_TOT * 32 * 4);
        const uint32_t* srcL = g_Al + (size_t)mb0 * (KS_TOT * 32 * 4);
        for (int u = tid; u < 4096; u += 512) {
            cpasync16(sA + u * 16, srcH + u * 4);
            cpasync16(sA + 65536 + u * 16, srcL + u * 4);
        }
        asm volatile("cp.async.commit_group;" ::: "memory");
    }

    uint4 bnxt[4];
    loadB_step(bnxt, it0, 0, nwarp, lane);    // overlaps the A cp.async

    asm volatile("cp.async.wait_group 0;" ::: "memory");
    __syncthreads();                           // last barrier before epilogue

    float best[2][2];
    int   bidx[2][2];
#pragma unroll
    for (int mf = 0; mf < 2; ++mf)
#pragma unroll
        for (int hh = 0; hh < 2; ++hh) { best[mf][hh] = 3.402823466e+38f; bidx[mf][hh] = 0; }

    float acc[2][4][4];

    for (int ii = 0; ii < NITERL; ++ii) {
        const int it = it0 + ii;
        const int ntile = it >> 3, kspair = it & 7;

        if (kspair == 0) {
#pragma unroll
            for (int mf = 0; mf < 2; ++mf)
#pragma unroll
                for (int nf = 0; nf < 4; ++nf)
#pragma unroll
                    for (int c = 0; c < 4; ++c) acc[mf][nf][c] = 0.f;
        }

#pragma unroll
        for (int ksl = 0; ksl < 2; ++ksl) {
            const int ks = kspair * 2 + ksl;

            // Rotate register pipeline; prefetch next ksl-step's B from L2.
            uint4 bcur[4];
#pragma unroll
            for (int q = 0; q < 4; ++q) bcur[q] = bnxt[q];
            {
                const int gs = ii * 2 + ksl + 1;   // next ksl-step index
                if (gs < NGS) {
                    const int nit = it0 + (gs >> 1);
                    const int nks = ((nit & 7) * 2) + (gs & 1);
                    loadB_step(bnxt, nit, nks, nwarp, lane);
                }
            }

            uint32_t ah[2][4], al[2][4];
#pragma unroll
            for (int mf = 0; mf < 2; ++mf) {
                int idx = ((((mwarp * 2 + mf) * 16 + ks) * 32 + lane)) * 4;
                *(uint4*)ah[mf] = *(const uint4*)(As + idx);
                *(uint4*)al[mf] = *(const uint4*)(As + 16384 + idx);
            }
#pragma unroll
            for (int mf = 0; mf < 2; ++mf)
#pragma unroll
                for (int nf = 0; nf < 4; ++nf) {
                    const uint32_t* bb = (const uint32_t*)&bcur[nf];
                    mma16816(acc[mf][nf], ah[mf], bb);        // hi*hi
                    mma16816(acc[mf][nf], ah[mf], bb + 2);    // hi*lo
                    mma16816(acc[mf][nf], al[mf], bb);        // lo*hi
                }
        }

        // End of n-tile: fold distances into running argmin (k ascending).
        if (kspair == 7) {
#pragma unroll
            for (int mf = 0; mf < 2; ++mf) {
#pragma unroll
                for (int nf = 0; nf < 4; ++nf) {
                    const int k0 = ntile * NT + (nwarp * 4 + nf) * 8 + tig * 2;
                    float c0 = __ldg(&g_csq[k0]);
                    float c1 = __ldg(&g_csq[k0 + 1]);
                    float m00 = fmaf(-2.f, acc[mf][nf][0], c0);
                    float m01 = fmaf(-2.f, acc[mf][nf][1], c1);
                    float m10 = fmaf(-2.f, acc[mf][nf][2], c0);
                    float m11 = fmaf(-2.f, acc[mf][nf][3], c1);
                    if (m00 < best[mf][0]) { best[mf][0] = m00; bidx[mf][0] = k0; }
                    if (m01 < best[mf][0]) { best[mf][0] = m01; bidx[mf][0] = k0 + 1; }
                    if (m10 < best[mf][1]) { best[mf][1] = m10; bidx[mf][1] = k0; }
                    if (m11 < best[mf][1]) { best[mf][1] = m11; bidx[mf][1] = k0 + 1; }
                }
            }
        }
    }

    // Two-level argmin merge: shfl across tig lanes -> smem -> global key.
#pragma unroll
    for (int mf = 0; mf < 2; ++mf) {
#pragma unroll
        for (int hh = 0; hh < 2; ++hh) {
            float bv = best[mf][hh];
            int   bi = bidx[mf][hh];
#pragma unroll
            for (int off = 1; off <= 2; off <<= 1) {
                float ov = __shfl_xor_sync(0xffffffffu, bv, off);
                int   oi = __shfl_xor_sync(0xffffffffu, bi, off);
                if (ov < bv || (ov == bv && oi < bi)) { bv = ov; bi = oi; }
            }
            if (tig == 0) {
                int row = (mwarp * 2 + mf) * 16 + gid + hh * 8;
                unsigned long long key =
                    ((unsigned long long)fkey(bv) << 32) | (unsigned)bi;
                atomicMin(&red[row], key);
            }
        }
    }
    __syncthreads();
    if (tid < MT) atomicMin(&g_key[n0 + tid], red[tid]);
}

// ---------------------------------------------------------------------------
// Outputs (4 tokens per thread, vectorized): exact fp32 op order for STE.
// ---------------------------------------------------------------------------
__global__ void vq_gather_kernel(const float* __restrict__ x,
                                 const float* __restrict__ E,
                                 float* __restrict__ out) {
    size_t t = (size_t)blockIdx.x * blockDim.x + threadIdx.x;  // D_*NTOK/4
    int n4 = (int)(t & (NTOK / 4 - 1));
    int d  = (int)(t >> 12);
    int n  = n4 * 4;
    int b = n >> 10;
    int s = n & (S_ - 1);
    int i0 = (int)(g_key[n]     & 0xFFFFFFFFu);
    int i1 = (int)(g_key[n + 1] & 0xFFFFFFFFu);
    int i2 = (int)(g_key[n + 2] & 0xFFFFFFFFu);
    int i3 = (int)(g_key[n + 3] & 0xFFFFFFFFu);
    const float* Ed = E + (size_t)d * KC;
    float4 q = make_float4(Ed[i0], Ed[i1], Ed[i2], Ed[i3]);
    size_t xo = ((size_t)b * D_ + d) * S_ + s;
    float4 xv = *(const float4*)&x[xo];
    float4 o1 = make_float4(xv.x + (q.x - xv.x), xv.y + (q.y - xv.y),
                            xv.z + (q.z - xv.z), xv.w + (q.w - xv.w));
    *(float4*)&out[xo]       = o1;
    *(float4*)&out[BDS + xo] = q;
    if (d == 0)
        *(float4*)&out[2 * (size_t)BDS + n] =
            make_float4((float)i0, (float)i1, (float)i2, (float)i3);
}

// ---------------------------------------------------------------------------
extern "C" void kernel_launch(void* const* d_in, const int* in_sizes, int n_in,
                              void* d_out, int out_size) {
    const float* x = (const float*)d_in[0];   // [B, D, H, W] fp32
    const float* E = (const float*)d_in[1];   // [D, K] fp32
    float* out = (float*)d_out;

    cudaFuncSetAttribute(vq_mma_kernel,
                         cudaFuncAttributeMaxDynamicSharedMemorySize, SMEM_MAIN);

    vq_split_x<<<MB_TOT, 256>>>(x);
    vq_split_e<<<(NB_TOT * 16 * 32) / 256, 256>>>(E);
    vq_csq_kernel<<<KC / 256, 256>>>(E);
    vq_mma_kernel<<<(NTOK / MT) * NPARTS, 512, SMEM_MAIN>>>();
    vq_gather_kernel<<<(D_ * NTOK / 4) / 256, 256>>>(x, E, out);
}

// round 10
// speedup vs baseline: 1.0772x; 1.0772x over previous
#include <cuda_runtime.h>
#include <cuda_fp16.h>
#include <cstdint>

// Problem constants
#define B_    16
#define D_    256
#define S_    1024
#define NTOK  16384
#define KC    8192
#define BDS   4194304

#define MB_TOT (NTOK / 16)        // 1024 token blocks of 16
#define KS_TOT (D_ / 16)          // 16 k-steps of 16
#define NB_TOT (KC / 8)           // 1024 code blocks of 8

// Main kernel tiling (R8 configuration: 8 warps, 4m x 4n warp microtiles)
#define MT     128                // tokens per block
#define NT     128                // codes per n-tile
#define NPARTS 8                  // codebook split per token tile
#define NITERL 64                 // local iterations (2 k-steps each)

// smem layout (bytes): A-tile (hi|lo) + reduction slots
#define SMEM_A_BYTES 131072       // [2 h][8 mb][16 ks][32 lane][4] u32
#define SMEM_RED     1024         // 128 x u64
#define SMEM_MAIN (SMEM_A_BYTES + SMEM_RED)

// Device scratch (allocations forbidden)
__device__ uint32_t g_Ah[MB_TOT * KS_TOT * 32 * 4];   // 8 MB
__device__ uint32_t g_Al[MB_TOT * KS_TOT * 32 * 4];   // 8 MB
__device__ uint32_t g_B [NB_TOT * KS_TOT * 32 * 4];   // 8 MB: {bh0,bh1,bl0,bl1}
__device__ float    g_csq[KC];
__device__ unsigned long long g_key[NTOK];            // packed (fkey(dist)<<32 | k)

// ---------------------------- helpers --------------------------------------
__device__ __forceinline__ uint32_t smem_u32(const void* p) {
    uint32_t a;
    asm("{ .reg .u64 t; cvta.to.shared.u64 t, %1; cvt.u32.u64 %0, t; }" : "=r"(a) : "l"(p));
    return a;
}
__device__ __forceinline__ void cpasync16(uint32_t dst, const void* src) {
    asm volatile("cp.async.cg.shared.global [%0], [%1], 16;" :: "r"(dst), "l"(src));
}
__device__ __forceinline__ void mma16816(float* c, const uint32_t* a, const uint32_t* b) {
    asm volatile("mma.sync.aligned.m16n8k16.row.col.f32.f16.f16.f32 "
                 "{%0,%1,%2,%3}, {%4,%5,%6,%7}, {%8,%9}, {%0,%1,%2,%3};"
                 : "+f"(c[0]), "+f"(c[1]), "+f"(c[2]), "+f"(c[3])
                 : "r"(a[0]), "r"(a[1]), "r"(a[2]), "r"(a[3]), "r"(b[0]), "r"(b[1]));
}
__device__ __forceinline__ uint32_t pack_h2(__half lo, __half hi) {
    __half2 h = __halves2half2(lo, hi);
    return *reinterpret_cast<uint32_t*>(&h);
}
__device__ __forceinline__ void split16(float v, __half& h, __half& l) {
    h = __float2half_rn(v);
    l = __float2half_rn(v - __half2float(h));
}
__device__ __forceinline__ unsigned int fkey(float f) {
    unsigned u = __float_as_uint(f);
    return (u & 0x80000000u) ? ~u : (u | 0x80000000u);
}

// ---------------------------------------------------------------------------
// Split x into fp16 hi/lo A-fragments (mma m16n8k16 row-major A layout).
// Also re-initializes g_key every launch (blocks 0..63).
// ---------------------------------------------------------------------------
__global__ void vq_split_x(const float* __restrict__ x) {
    __shared__ float xs[D_ * 16];            // [d][tok]
    const int mb = blockIdx.x;
    const int t0 = mb * 16;
    const int b  = t0 >> 10;
    const int s0 = t0 & (S_ - 1);
    const int tid = threadIdx.x;

    if (mb < NTOK / 256) g_key[mb * 256 + tid] = 0xFFFFFFFFFFFFFFFFULL;

    for (int i = tid; i < D_ * 16; i += 256) {
        int d = i >> 4, tok = i & 15;
        xs[d * 16 + tok] = x[((size_t)b * D_ + d) * S_ + s0 + tok];
    }
    __syncthreads();

    const size_t obase = (size_t)mb * (KS_TOT * 32 * 4);
    for (int oi = tid; oi < KS_TOT * 32 * 4; oi += 256) {
        int ks = oi >> 7, rem = oi & 127;
        int lane = rem >> 2, r = rem & 3;
        int gid = lane >> 2, tig = lane & 3;
        int row = gid + (r & 1) * 8;
        int c0  = ks * 16 + tig * 2 + (r >> 1) * 8;
        float v0 = xs[c0 * 16 + row];
        float v1 = xs[(c0 + 1) * 16 + row];
        __half h0, l0, h1, l1;
        split16(v0, h0, l0);
        split16(v1, h1, l1);
        g_Ah[obase + oi] = pack_h2(h0, h1);
        g_Al[obase + oi] = pack_h2(l0, l1);
    }
}

// ---------------------------------------------------------------------------
// Split E into interleaved fp16 hi/lo B-fragments AND compute csq, fused.
// Block = 32 codes x full D, staged through smem (coalesced E reads, coalesced
// uint4 fragment writes). Grid = KC/32 = 256 blocks.
// ---------------------------------------------------------------------------
__global__ void vq_split_e(const float* __restrict__ E) {
    __shared__ float es[D_ * 33 / 32 * 32];  // [256][33] padded rows
    __shared__ float cred[8][32];
    const int k0  = blockIdx.x * 32;
    const int tid = threadIdx.x;

    // Coalesced load: 256 rows x 32 codes.
    for (int i = tid; i < D_ * 32; i += 256) {
        int d = i >> 5, kk = i & 31;
        es[d * 33 + kk] = E[(size_t)d * KC + k0 + kk];
    }
    __syncthreads();

    // csq: deterministic part-ordered sum of squares per code column.
    {
        const int kk = tid & 31, part = tid >> 5;
        float s = 0.f;
#pragma unroll 8
        for (int dd = 0; dd < 32; ++dd) {
            float v = es[(part * 32 + dd) * 33 + kk];
            s = fmaf(v, v, s);
        }
        cred[part][kk] = s;
    }
    __syncthreads();
    if (tid < 32) {
        float s = cred[0][tid];
#pragma unroll
        for (int p = 1; p < 8; ++p) s += cred[p][tid];
        g_csq[k0 + tid] = s;
    }

    // Fragments: 4 nb x 16 ks x 32 lane = 2048 uint4, coalesced writes.
    for (int fi = tid; fi < 2048; fi += 256) {
        int nbl  = fi >> 9;
        int rem  = fi & 511;
        int ks   = rem >> 5;
        int lane = rem & 31;
        int gid = lane >> 2, tig = lane & 3;
        int kl  = nbl * 8 + gid;
        uint32_t frag[4];
#pragma unroll
        for (int r = 0; r < 2; ++r) {
            int d0 = ks * 16 + tig * 2 + r * 8;
            float v0 = es[d0 * 33 + kl];
            float v1 = es[(d0 + 1) * 33 + kl];
            __half h0, l0, h1, l1;
            split16(v0, h0, l0);
            split16(v1, h1, l1);
            frag[r]     = pack_h2(h0, h1);
            frag[2 + r] = pack_h2(l0, l1);
        }
        *(uint4*)&g_B[((size_t)blockIdx.x * 2048 + fi) * 4] = *(uint4*)frag;
    }
}

// ---------------------------------------------------------------------------
// Main kernel (R8 config): 256 threads (8 warps, 2m x 4n), MT=128 A-tile in
// smem; B register-pipelined one iteration ahead via LDG.128; barrier-free
// mainloop; block = (token tile, codebook eighth); grid = 1024.
// ---------------------------------------------------------------------------
__device__ __forceinline__ void loadB(uint4* b, int it, int nwarp, int lane) {
    const int ntile = it >> 3, kspair = it & 7;
    const uint32_t* base = g_B +
        ((size_t)(((ntile * 16 + nwarp * 4) * 16 + kspair * 2) * 32 + lane)) * 4;
#pragma unroll
    for (int nf = 0; nf < 4; ++nf)
#pragma unroll
        for (int ksl = 0; ksl < 2; ++ksl)
            b[nf * 2 + ksl] = __ldg((const uint4*)(base + nf * 2048 + ksl * 128));
}

__global__ __launch_bounds__(256, 1) void vq_mma_kernel() {
    extern __shared__ char smem[];
    uint32_t* As = (uint32_t*)smem;
    unsigned long long* red = (unsigned long long*)(smem + SMEM_A_BYTES);
    const uint32_t sA = smem_u32(As);

    const int tid = threadIdx.x;
    const int wid = tid >> 5, lane = tid & 31;
    const int gid = lane >> 2, tig = lane & 3;
    const int mwarp = wid >> 2, nwarp = wid & 3;

    const int bx = blockIdx.x;                // 0..1023
    const int part   = bx & (NPARTS - 1);     // codebook eighth
    const int tileid = bx >> 3;               // token tile
    const int mb0 = tileid * 8;
    const int n0  = tileid * MT;
    const int it0 = part * NITERL;            // global iteration base

    for (int i = tid; i < MT; i += 256) red[i] = 0xFFFFFFFFFFFFFFFFULL;

    // Prologue: A resident tile (hi+lo, 128 KB) via cp.async; single barrier.
    {
        const uint32_t* srcH = g_Ah + (size_t)mb0 * (KS_TOT * 32 * 4);
        const uint32_t* srcL = g_Al + (size_t)mb0 * (KS_TOT * 32 * 4);
        for (int u = tid; u < 4096; u += 256) {
            cpasync16(sA + u * 16, srcH + u * 4);
            cpasync16(sA + 65536 + u * 16, srcL + u * 4);
        }
        asm volatile("cp.async.commit_group;" ::: "memory");
    }

    uint4 bnxt[8];
    loadB(bnxt, it0, nwarp, lane);            // overlaps the A cp.async

    asm volatile("cp.async.wait_group 0;" ::: "memory");
    __syncthreads();                           // last barrier before epilogue

    float best[4][2];
    int   bidx[4][2];
#pragma unroll
    for (int mf = 0; mf < 4; ++mf)
#pragma unroll
        for (int hh = 0; hh < 2; ++hh) { best[mf][hh] = 3.402823466e+38f; bidx[mf][hh] = 0; }

    float acc[4][4][4];

    for (int ii = 0; ii < NITERL; ++ii) {
        const int it = it0 + ii;
        const int ntile = it >> 3, kspair = it & 7;

        // Rotate register pipeline; prefetch next iteration's B from L2.
        uint4 bcur[8];
#pragma unroll
        for (int q = 0; q < 8; ++q) bcur[q] = bnxt[q];
        if (ii + 1 < NITERL) loadB(bnxt, it + 1, nwarp, lane);

        if (kspair == 0) {
#pragma unroll
            for (int mf = 0; mf < 4; ++mf)
#pragma unroll
                for (int nf = 0; nf < 4; ++nf)
#pragma unroll
                    for (int c = 0; c < 4; ++c) acc[mf][nf][c] = 0.f;
        }

#pragma unroll
        for (int ksl = 0; ksl < 2; ++ksl) {
            const int ks = kspair * 2 + ksl;
            uint32_t ah[4][4], al[4][4];
#pragma unroll
            for (int mf = 0; mf < 4; ++mf) {
                int idx = (((mwarp * 4 + mf) * 16 + ks) * 32 + lane) * 4;
                *(uint4*)ah[mf] = *(const uint4*)(As + idx);
                *(uint4*)al[mf] = *(const uint4*)(As + 16384 + idx);
            }
#pragma unroll
            for (int mf = 0; mf < 4; ++mf)
#pragma unroll
                for (int nf = 0; nf < 4; ++nf) {
                    const uint32_t* bb = (const uint32_t*)&bcur[nf * 2 + ksl];
                    mma16816(acc[mf][nf], ah[mf], bb);        // hi*hi
                    mma16816(acc[mf][nf], ah[mf], bb + 2);    // hi*lo
                    mma16816(acc[mf][nf], al[mf], bb);        // lo*hi
                }
        }

        // End of n-tile: fold distances into running argmin (k ascending).
        if (kspair == 7) {
#pragma unroll
            for (int mf = 0; mf < 4; ++mf) {
#pragma unroll
                for (int nf = 0; nf < 4; ++nf) {
                    const int k0 = ntile * NT + (nwarp * 4 + nf) * 8 + tig * 2;
                    float c0 = __ldg(&g_csq[k0]);
                    float c1 = __ldg(&g_csq[k0 + 1]);
                    float m00 = fmaf(-2.f, acc[mf][nf][0], c0);
                    float m01 = fmaf(-2.f, acc[mf][nf][1], c1);
                    float m10 = fmaf(-2.f, acc[mf][nf][2], c0);
                    float m11 = fmaf(-2.f, acc[mf][nf][3], c1);
                    if (m00 < best[mf][0]) { best[mf][0] = m00; bidx[mf][0] = k0; }
                    if (m01 < best[mf][0]) { best[mf][0] = m01; bidx[mf][0] = k0 + 1; }
                    if (m10 < best[mf][1]) { best[mf][1] = m10; bidx[mf][1] = k0; }
                    if (m11 < best[mf][1]) { best[mf][1] = m11; bidx[mf][1] = k0 + 1; }
                }
            }
        }
    }

    // Two-level argmin merge: shfl across tig lanes -> smem -> global key.
#pragma unroll
    for (int mf = 0; mf < 4; ++mf) {
#pragma unroll
        for (int hh = 0; hh < 2; ++hh) {
            float bv = best[mf][hh];
            int   bi = bidx[mf][hh];
#pragma unroll
            for (int off = 1; off <= 2; off <<= 1) {
                float ov = __shfl_xor_sync(0xffffffffu, bv, off);
                int   oi = __shfl_xor_sync(0xffffffffu, bi, off);
                if (ov < bv || (ov == bv && oi < bi)) { bv = ov; bi = oi; }
            }
            if (tig == 0) {
                int row = mwarp * 64 + mf * 16 + gid + hh * 8;
                unsigned long long key =
                    ((unsigned long long)fkey(bv) << 32) | (unsigned)bi;
                atomicMin(&red[row], key);
            }
        }
    }
    __syncthreads();
    if (tid < MT) atomicMin(&g_key[n0 + tid], red[tid]);
}

// ---------------------------------------------------------------------------
// Outputs (4 tokens per thread, vectorized): exact fp32 op order for STE.
// ---------------------------------------------------------------------------
__global__ void vq_gather_kernel(const float* __restrict__ x,
                                 const float* __restrict__ E,
                                 float* __restrict__ out) {
    size_t t = (size_t)blockIdx.x * blockDim.x + threadIdx.x;  // D_*NTOK/4
    int n4 = (int)(t & (NTOK / 4 - 1));
    int d  = (int)(t >> 12);
    int n  = n4 * 4;
    int b = n >> 10;
    int s = n & (S_ - 1);
    int i0 = (int)(g_key[n]     & 0xFFFFFFFFu);
    int i1 = (int)(g_key[n + 1] & 0xFFFFFFFFu);
    int i2 = (int)(g_key[n + 2] & 0xFFFFFFFFu);
    int i3 = (int)(g_key[n + 3] & 0xFFFFFFFFu);
    const float* Ed = E + (size_t)d * KC;
    float4 q = make_float4(Ed[i0], Ed[i1], Ed[i2], Ed[i3]);
    size_t xo = ((size_t)b * D_ + d) * S_ + s;
    float4 xv = *(const float4*)&x[xo];
    float4 o1 = make_float4(xv.x + (q.x - xv.x), xv.y + (q.y - xv.y),
                            xv.z + (q.z - xv.z), xv.w + (q.w - xv.w));
    *(float4*)&out[xo]       = o1;
    *(float4*)&out[BDS + xo] = q;
    if (d == 0)
        *(float4*)&out[2 * (size_t)BDS + n] =
            make_float4((float)i0, (float)i1, (float)i2, (float)i3);
}

// ---------------------------------------------------------------------------
extern "C" void kernel_launch(void* const* d_in, const int* in_sizes, int n_in,
                              void* d_out, int out_size) {
    const float* x = (const float*)d_in[0];   // [B, D, H, W] fp32
    const float* E = (const float*)d_in[1];   // [D, K] fp32
    float* out = (float*)d_out;

    cudaFuncSetAttribute(vq_mma_kernel,
                         cudaFuncAttributeMaxDynamicSharedMemorySize, SMEM_MAIN);

    vq_split_x<<<MB_TOT, 256>>>(x);
    vq_split_e<<<KC / 32, 256>>>(E);
    vq_mma_kernel<<<(NTOK / MT) * NPARTS, 256, SMEM_MAIN>>>();
    vq_gather_kernel<<<(D_ * NTOK / 4) / 256, 256>>>(x, E, out);
}

// round 11
// speedup vs baseline: 1.0835x; 1.0058x over previous
#include <cuda_runtime.h>
#include <cuda_fp16.h>
#include <cstdint>

// Problem constants
#define B_    16
#define D_    256
#define S_    1024
#define NTOK  16384
#define KC    8192
#define BDS   4194304

#define MB_TOT (NTOK / 16)        // 1024 token blocks of 16
#define KS_TOT (D_ / 16)          // 16 k-steps of 16
#define NB_TOT (KC / 8)           // 1024 code blocks of 8

// Main kernel tiling (8 warps, 4m x 4n warp microtiles)
#define MT     128                // tokens per block
#define NT     128                // codes per n-tile
#define NPARTS 8                  // codebook split per token tile
#define NITERL 64                 // local iterations (2 k-steps each)

// smem layout (bytes): A-tile (hi|lo) + reduction slots
#define SMEM_A_BYTES 131072       // [2 h][8 mb][16 ks][32 lane][4] u32
#define SMEM_RED     1024         // 128 x u64
#define SMEM_MAIN (SMEM_A_BYTES + SMEM_RED)

// Device scratch (allocations forbidden)
__device__ uint32_t g_Ah[MB_TOT * KS_TOT * 32 * 4];   // 8 MB
__device__ uint32_t g_Al[MB_TOT * KS_TOT * 32 * 4];   // 8 MB
__device__ uint32_t g_B [NB_TOT * KS_TOT * 32 * 4];   // 8 MB: {bh0,bh1,bl0,bl1}
__device__ float    g_csq[KC];
__device__ unsigned long long g_key[NTOK];            // packed (fkey(dist)<<32 | k)

// ---------------------------- helpers --------------------------------------
__device__ __forceinline__ uint32_t smem_u32(const void* p) {
    uint32_t a;
    asm("{ .reg .u64 t; cvta.to.shared.u64 t, %1; cvt.u32.u64 %0, t; }" : "=r"(a) : "l"(p));
    return a;
}
__device__ __forceinline__ void cpasync16(uint32_t dst, const void* src) {
    asm volatile("cp.async.cg.shared.global [%0], [%1], 16;" :: "r"(dst), "l"(src));
}
__device__ __forceinline__ void mma16816(float* c, const uint32_t* a, const uint32_t* b) {
    asm volatile("mma.sync.aligned.m16n8k16.row.col.f32.f16.f16.f32 "
                 "{%0,%1,%2,%3}, {%4,%5,%6,%7}, {%8,%9}, {%0,%1,%2,%3};"
                 : "+f"(c[0]), "+f"(c[1]), "+f"(c[2]), "+f"(c[3])
                 : "r"(a[0]), "r"(a[1]), "r"(a[2]), "r"(a[3]), "r"(b[0]), "r"(b[1]));
}
__device__ __forceinline__ uint32_t pack_h2(__half lo, __half hi) {
    __half2 h = __halves2half2(lo, hi);
    return *reinterpret_cast<uint32_t*>(&h);
}
__device__ __forceinline__ void split16(float v, __half& h, __half& l) {
    h = __float2half_rn(v);
    l = __float2half_rn(v - __half2float(h));
}
__device__ __forceinline__ unsigned int fkey(float f) {
    unsigned u = __float_as_uint(f);
    return (u & 0x80000000u) ? ~u : (u | 0x80000000u);
}

// ---------------------------------------------------------------------------
// Fused preprocessing kernel. Blocks [0, MB_TOT): x -> A-fragments (+g_key
// init). Blocks [MB_TOT, MB_TOT+KC/32): E -> B-fragments + csq. The two
// independent phases overlap on the grid.
// ---------------------------------------------------------------------------
__global__ void vq_split_xe(const float* __restrict__ x,
                            const float* __restrict__ E) {
    __shared__ char sm[36000];
    const int tid = threadIdx.x;

    if (blockIdx.x < MB_TOT) {
        float* xs = (float*)sm;                  // [d][tok] 16 KB
        const int mb = blockIdx.x;
        const int t0 = mb * 16;
        const int b  = t0 >> 10;
        const int s0 = t0 & (S_ - 1);

        if (mb < NTOK / 256) g_key[mb * 256 + tid] = 0xFFFFFFFFFFFFFFFFULL;

        for (int i = tid; i < D_ * 16; i += 256) {
            int d = i >> 4, tok = i & 15;
            xs[d * 16 + tok] = x[((size_t)b * D_ + d) * S_ + s0 + tok];
        }
        __syncthreads();

        const size_t obase = (size_t)mb * (KS_TOT * 32 * 4);
        for (int oi = tid; oi < KS_TOT * 32 * 4; oi += 256) {
            int ks = oi >> 7, rem = oi & 127;
            int lane = rem >> 2, r = rem & 3;
            int gid = lane >> 2, tig = lane & 3;
            int row = gid + (r & 1) * 8;
            int c0  = ks * 16 + tig * 2 + (r >> 1) * 8;
            float v0 = xs[c0 * 16 + row];
            float v1 = xs[(c0 + 1) * 16 + row];
            __half h0, l0, h1, l1;
            split16(v0, h0, l0);
            split16(v1, h1, l1);
            g_Ah[obase + oi] = pack_h2(h0, h1);
            g_Al[obase + oi] = pack_h2(l0, l1);
        }
    } else {
        float* es   = (float*)sm;                // [256][33] padded, 33.8 KB
        float* cred = (float*)(sm + 33792);      // [8][32]
        const int eb = blockIdx.x - MB_TOT;
        const int k0 = eb * 32;

        for (int i = tid; i < D_ * 32; i += 256) {
            int d = i >> 5, kk = i & 31;
            es[d * 33 + kk] = E[(size_t)d * KC + k0 + kk];
        }
        __syncthreads();

        {   // csq: deterministic part-ordered sum of squares per code column.
            const int kk = tid & 31, part = tid >> 5;
            float s = 0.f;
#pragma unroll 8
            for (int dd = 0; dd < 32; ++dd) {
                float v = es[(part * 32 + dd) * 33 + kk];
                s = fmaf(v, v, s);
            }
            cred[part * 32 + kk] = s;
        }
        __syncthreads();
        if (tid < 32) {
            float s = cred[tid];
#pragma unroll
            for (int p = 1; p < 8; ++p) s += cred[p * 32 + tid];
            g_csq[k0 + tid] = s;
        }

        // Fragments: 4 nb x 16 ks x 32 lane = 2048 uint4, coalesced writes.
        for (int fi = tid; fi < 2048; fi += 256) {
            int nbl  = fi >> 9;
            int rem  = fi & 511;
            int ks   = rem >> 5;
            int lane = rem & 31;
            int gid = lane >> 2, tig = lane & 3;
            int kl  = nbl * 8 + gid;
            uint32_t frag[4];
#pragma unroll
            for (int r = 0; r < 2; ++r) {
                int d0 = ks * 16 + tig * 2 + r * 8;
                float v0 = es[d0 * 33 + kl];
                float v1 = es[(d0 + 1) * 33 + kl];
                __half h0, l0, h1, l1;
                split16(v0, h0, l0);
                split16(v1, h1, l1);
                frag[r]     = pack_h2(h0, h1);
                frag[2 + r] = pack_h2(l0, l1);
            }
            *(uint4*)&g_B[((size_t)eb * 2048 + fi) * 4] = *(uint4*)frag;
        }
    }
}

// ---------------------------------------------------------------------------
// Main kernel: 256 threads (8 warps, 2m x 4n), MT=128 A-tile in smem;
// B register-pipelined one iteration ahead via LDG.128; barrier-free
// mainloop; two-group A prologue with early start on the first half.
// ---------------------------------------------------------------------------
__device__ __forceinline__ void loadB(uint4* b, int it, int nwarp, int lane) {
    const int ntile = it >> 3, kspair = it & 7;
    const uint32_t* base = g_B +
        ((size_t)(((ntile * 16 + nwarp * 4) * 16 + kspair * 2) * 32 + lane)) * 4;
#pragma unroll
    for (int nf = 0; nf < 4; ++nf)
#pragma unroll
        for (int ksl = 0; ksl < 2; ++ksl)
            b[nf * 2 + ksl] = __ldg((const uint4*)(base + nf * 2048 + ksl * 128));
}

// One mainloop iteration (math path identical to R8/R10).
#define MMA_ITER(II)                                                          \
    do {                                                                      \
        const int it = it0 + (II);                                            \
        const int ntile = it >> 3, kspair = it & 7;                           \
        uint4 bcur[8];                                                        \
        _Pragma("unroll")                                                     \
        for (int q = 0; q < 8; ++q) bcur[q] = bnxt[q];                        \
        if ((II) + 1 < NITERL) loadB(bnxt, it + 1, nwarp, lane);              \
        if (kspair == 0) {                                                    \
            _Pragma("unroll")                                                 \
            for (int mf = 0; mf < 4; ++mf)                                    \
                _Pragma("unroll")                                             \
                for (int nf = 0; nf < 4; ++nf)                                \
                    _Pragma("unroll")                                         \
                    for (int c = 0; c < 4; ++c) acc[mf][nf][c] = 0.f;         \
            _Pragma("unroll")                                                 \
            for (int nf = 0; nf < 4; ++nf) {                                  \
                int kq = ntile * NT + (nwarp * 4 + nf) * 8 + tig * 2;         \
                cregs[nf][0] = __ldg(&g_csq[kq]);                             \
                cregs[nf][1] = __ldg(&g_csq[kq + 1]);                         \
            }                                                                 \
        }                                                                     \
        _Pragma("unroll")                                                     \
        for (int ksl = 0; ksl < 2; ++ksl) {                                   \
            const int ks = kspair * 2 + ksl;                                  \
            uint32_t ah[4][4], al[4][4];                                      \
            _Pragma("unroll")                                                 \
            for (int mf = 0; mf < 4; ++mf) {                                  \
                int idx = (((mwarp * 4 + mf) * 16 + ks) * 32 + lane) * 4;     \
                *(uint4*)ah[mf] = *(const uint4*)(As + idx);                  \
                *(uint4*)al[mf] = *(const uint4*)(As + 16384 + idx);          \
            }                                                                 \
            _Pragma("unroll")                                                 \
            for (int mf = 0; mf < 4; ++mf)                                    \
                _Pragma("unroll")                                             \
                for (int nf = 0; nf < 4; ++nf) {                              \
                    const uint32_t* bb = (const uint32_t*)&bcur[nf * 2 + ksl];\
                    mma16816(acc[mf][nf], ah[mf], bb);                        \
                    mma16816(acc[mf][nf], ah[mf], bb + 2);                    \
                    mma16816(acc[mf][nf], al[mf], bb);                        \
                }                                                             \
        }                                                                     \
        if (kspair == 7) {                                                    \
            _Pragma("unroll")                                                 \
            for (int mf = 0; mf < 4; ++mf) {                                  \
                _Pragma("unroll")                                             \
                for (int nf = 0; nf < 4; ++nf) {                              \
                    const int k0 = ntile * NT + (nwarp * 4 + nf) * 8 + tig * 2;\
                    float m00 = fmaf(-2.f, acc[mf][nf][0], cregs[nf][0]);     \
                    float m01 = fmaf(-2.f, acc[mf][nf][1], cregs[nf][1]);     \
                    float m10 = fmaf(-2.f, acc[mf][nf][2], cregs[nf][0]);     \
                    float m11 = fmaf(-2.f, acc[mf][nf][3], cregs[nf][1]);     \
                    if (m00 < best[mf][0]) { best[mf][0] = m00; bidx[mf][0] = k0; }      \
                    if (m01 < best[mf][0]) { best[mf][0] = m01; bidx[mf][0] = k0 + 1; }  \
                    if (m10 < best[mf][1]) { best[mf][1] = m10; bidx[mf][1] = k0; }      \
                    if (m11 < best[mf][1]) { best[mf][1] = m11; bidx[mf][1] = k0 + 1; }  \
                }                                                             \
            }                                                                 \
        }                                                                     \
    } while (0)

__global__ __launch_bounds__(256, 1) void vq_mma_kernel() {
    extern __shared__ char smem[];
    uint32_t* As = (uint32_t*)smem;
    unsigned long long* red = (unsigned long long*)(smem + SMEM_A_BYTES);
    const uint32_t sA = smem_u32(As);

    const int tid = threadIdx.x;
    const int wid = tid >> 5, lane = tid & 31;
    const int gid = lane >> 2, tig = lane & 3;
    const int mwarp = wid >> 2, nwarp = wid & 3;

    const int bx = blockIdx.x;                // 0..1023
    const int part   = bx & (NPARTS - 1);     // codebook eighth
    const int tileid = bx >> 3;               // token tile
    const int mb0 = tileid * 8;
    const int n0  = tileid * MT;
    const int it0 = part * NITERL;            // global iteration base

    for (int i = tid; i < MT; i += 256) red[i] = 0xFFFFFFFFFFFFFFFFULL;

    // B pipeline head first (LDGs in flight during the whole A prologue).
    uint4 bnxt[8];
    loadB(bnxt, it0, nwarp, lane);

    // A prologue in two commit groups: ks 0-7, then ks 8-15.
    {
        const uint32_t* srcH = g_Ah + (size_t)mb0 * (KS_TOT * 32 * 4);
        const uint32_t* srcL = g_Al + (size_t)mb0 * (KS_TOT * 32 * 4);
#pragma unroll
        for (int half = 0; half < 2; ++half) {
            for (int u = tid; u < 2048; u += 256) {
                int mb = u >> 8, ks = ((u >> 5) & 7) + half * 8, ln = u & 31;
                int unit = (mb * 16 + ks) * 32 + ln;     // 16-byte units
                cpasync16(sA + unit * 16, srcH + unit * 4);
                cpasync16(sA + 65536 + unit * 16, srcL + unit * 4);
            }
            asm volatile("cp.async.commit_group;" ::: "memory");
        }
    }

    float best[4][2];
    int   bidx[4][2];
#pragma unroll
    for (int mf = 0; mf < 4; ++mf)
#pragma unroll
        for (int hh = 0; hh < 2; ++hh) { best[mf][hh] = 3.402823466e+38f; bidx[mf][hh] = 0; }

    float acc[4][4][4];
    float cregs[4][2];

    // Start on the first half of A (iterations 0-3 touch only ks 0-7).
    asm volatile("cp.async.wait_group 1;" ::: "memory");
    __syncthreads();
#pragma unroll 1
    for (int ii = 0; ii < 4; ++ii) MMA_ITER(ii);

    asm volatile("cp.async.wait_group 0;" ::: "memory");
    __syncthreads();
#pragma unroll 1
    for (int ii = 4; ii < NITERL; ++ii) MMA_ITER(ii);

    // Two-level argmin merge: shfl across tig lanes -> smem -> global key.
#pragma unroll
    for (int mf = 0; mf < 4; ++mf) {
#pragma unroll
        for (int hh = 0; hh < 2; ++hh) {
            float bv = best[mf][hh];
            int   bi = bidx[mf][hh];
#pragma unroll
            for (int off = 1; off <= 2; off <<= 1) {
                float ov = __shfl_xor_sync(0xffffffffu, bv, off);
                int   oi = __shfl_xor_sync(0xffffffffu, bi, off);
                if (ov < bv || (ov == bv && oi < bi)) { bv = ov; bi = oi; }
            }
            if (tig == 0) {
                int row = mwarp * 64 + mf * 16 + gid + hh * 8;
                unsigned long long key =
                    ((unsigned long long)fkey(bv) << 32) | (unsigned)bi;
                atomicMin(&red[row], key);
            }
        }
    }
    __syncthreads();
    if (tid < MT) atomicMin(&g_key[n0 + tid], red[tid]);
}

// ---------------------------------------------------------------------------
// Outputs (4 tokens per thread, vectorized): exact fp32 op order for STE.
// ---------------------------------------------------------------------------
__global__ void vq_gather_kernel(const float* __restrict__ x,
                                 const float* __restrict__ E,
                                 float* __restrict__ out) {
    size_t t = (size_t)blockIdx.x * blockDim.x + threadIdx.x;  // D_*NTOK/4
    int n4 = (int)(t & (NTOK / 4 - 1));
    int d  = (int)(t >> 12);
    int n  = n4 * 4;
    int b = n >> 10;
    int s = n & (S_ - 1);
    int i0 = (int)(g_key[n]     & 0xFFFFFFFFu);
    int i1 = (int)(g_key[n + 1] & 0xFFFFFFFFu);
    int i2 = (int)(g_key[n + 2] & 0xFFFFFFFFu);
    int i3 = (int)(g_key[n + 3] & 0xFFFFFFFFu);
    const float* Ed = E + (size_t)d * KC;
    float4 q = make_float4(Ed[i0], Ed[i1], Ed[i2], Ed[i3]);
    size_t xo = ((size_t)b * D_ + d) * S_ + s;
    float4 xv = *(const float4*)&x[xo];
    float4 o1 = make_float4(xv.x + (q.x - xv.x), xv.y + (q.y - xv.y),
                            xv.z + (q.z - xv.z), xv.w + (q.w - xv.w));
    *(float4*)&out[xo]       = o1;
    *(float4*)&out[BDS + xo] = q;
    if (d == 0)
        *(float4*)&out[2 * (size_t)BDS + n] =
            make_float4((float)i0, (float)i1, (float)i2, (float)i3);
}

// ---------------------------------------------------------------------------
extern "C" void kernel_launch(void* const* d_in, const int* in_sizes, int n_in,
                              void* d_out, int out_size) {
    const float* x = (const float*)d_in[0];   // [B, D, H, W] fp32
    const float* E = (const float*)d_in[1];   // [D, K] fp32
    float* out = (float*)d_out;

    cudaFuncSetAttribute(vq_mma_kernel,
                         cudaFuncAttributeMaxDynamicSharedMemorySize, SMEM_MAIN);

    vq_split_xe<<<MB_TOT + KC / 32, 256>>>(x, E);
    vq_mma_kernel<<<(NTOK / MT) * NPARTS, 256, SMEM_MAIN>>>();
    vq_gather_kernel<<<(D_ * NTOK / 4) / 256, 256>>>(x, E, out);
}